// round 7
// baseline (speedup 1.0000x reference)
#include <cuda_runtime.h>
#include <cuda_bf16.h>
#include <math.h>
#include <stdint.h>

// Problem constants
#define BB 2
#define SS 2048
#define EE 512
#define HH 8
#define DD 64
#define MM (BB * SS)   // 4096 rows

// Scratch (device globals; no allocation allowed)
__device__ float g_proj[MM * EE];

// bf16 hi/lo operand arrays
__device__ __align__(16) __nv_bfloat16 g_Ax_hi[MM * EE];       // x split (qkv gemm A)
__device__ __align__(16) __nv_bfloat16 g_Ax_lo[MM * EE];
__device__ __align__(16) __nv_bfloat16 g_Qh[16 * 2048 * 64];   // [bh][s][d]
__device__ __align__(16) __nv_bfloat16 g_Ql[16 * 2048 * 64];
__device__ __align__(16) __nv_bfloat16 g_Kh[16 * 2048 * 64];
__device__ __align__(16) __nv_bfloat16 g_Kl[16 * 2048 * 64];
__device__ __align__(16) __nv_bfloat16 g_Vh[16 * 2048 * 64];
__device__ __align__(16) __nv_bfloat16 g_Vl[16 * 2048 * 64];
__device__ __align__(16) __nv_bfloat16 g_Av_hi[MM * EE];       // attention out (proj A)
__device__ __align__(16) __nv_bfloat16 g_Av_lo[MM * EE];
__device__ __align__(16) __nv_bfloat16 g_Bqkv_hi[3 * EE * EE]; // [n=z*512+h*64+d][e]
__device__ __align__(16) __nv_bfloat16 g_Bqkv_lo[3 * EE * EE];
__device__ __align__(16) __nv_bfloat16 g_Bp_hi[EE * EE];       // [n][k] = Wp[n][k]
__device__ __align__(16) __nv_bfloat16 g_Bp_lo[EE * EE];

// ---------------------------------------------------------------------------
// helpers (sm_80-era: ldmatrix / mma.sync / cp.async)
// ---------------------------------------------------------------------------
__device__ __forceinline__ uint32_t smem_u32(const void* p) {
    uint32_t a;
    asm("{ .reg .u64 t; cvta.to.shared.u64 t, %1; cvt.u32.u64 %0, t; }"
        : "=r"(a) : "l"(p));
    return a;
}
__device__ __forceinline__ uint32_t sw128(uint32_t off) {
    return off ^ ((off >> 3) & 0x70);
}
__device__ __forceinline__ void cpasync16(uint32_t dst, const void* src) {
    asm volatile("cp.async.cg.shared.global [%0], [%1], 16;"
                 :: "r"(dst), "l"(src) : "memory");
}
template <int N>
__device__ __forceinline__ void waitg() {
    asm volatile("cp.async.wait_group %0;" :: "n"(N) : "memory");
}
__device__ __forceinline__ void commitg() {
    asm volatile("cp.async.commit_group;" ::: "memory");
}
__device__ __forceinline__ void ldsm4(uint32_t& r0, uint32_t& r1, uint32_t& r2,
                                      uint32_t& r3, uint32_t a) {
    asm volatile("ldmatrix.sync.aligned.m8n8.x4.shared.b16 {%0,%1,%2,%3}, [%4];"
                 : "=r"(r0), "=r"(r1), "=r"(r2), "=r"(r3) : "r"(a));
}
__device__ __forceinline__ void ldsm4t(uint32_t& r0, uint32_t& r1, uint32_t& r2,
                                       uint32_t& r3, uint32_t a) {
    asm volatile("ldmatrix.sync.aligned.m8n8.x4.trans.shared.b16 {%0,%1,%2,%3}, [%4];"
                 : "=r"(r0), "=r"(r1), "=r"(r2), "=r"(r3) : "r"(a));
}
__device__ __forceinline__ void mma16816(float* c, const uint32_t* a,
                                         uint32_t b0, uint32_t b1) {
    asm volatile(
        "mma.sync.aligned.m16n8k16.row.col.f32.bf16.bf16.f32 "
        "{%0,%1,%2,%3}, {%4,%5,%6,%7}, {%8,%9}, {%0,%1,%2,%3};"
        : "+f"(c[0]), "+f"(c[1]), "+f"(c[2]), "+f"(c[3])
        : "r"(a[0]), "r"(a[1]), "r"(a[2]), "r"(a[3]), "r"(b0), "r"(b1));
}
__device__ __forceinline__ void split2(float a, float b, uint32_t& hi, uint32_t& lo) {
    __nv_bfloat16 ha = __float2bfloat16(a), hb = __float2bfloat16(b);
    float ra = a - __bfloat162float(ha), rb = b - __bfloat162float(hb);
    hi = (uint32_t)__bfloat16_as_ushort(ha) |
         ((uint32_t)__bfloat16_as_ushort(hb) << 16);
    __nv_bfloat16 la = __float2bfloat16(ra), lb = __float2bfloat16(rb);
    lo = (uint32_t)__bfloat16_as_ushort(la) |
         ((uint32_t)__bfloat16_as_ushort(lb) << 16);
}

// ---------------------------------------------------------------------------
// Prep: weights + x -> bf16 hi/lo
// ---------------------------------------------------------------------------
__global__ void prep_wqkv_kernel(const float* __restrict__ Wq,
                                 const float* __restrict__ Wk,
                                 const float* __restrict__ Wv) {
    int idx = blockIdx.x * 256 + threadIdx.x;      // < 3*512*512
    int n = idx >> 9, e = idx & 511;
    int z = n >> 9, h = (n >> 6) & 7, d = n & 63;
    const float* W = (z == 0) ? Wq : ((z == 1) ? Wk : Wv);
    float v = W[((size_t)h * EE + e) * DD + d];
    __nv_bfloat16 hi = __float2bfloat16(v);
    g_Bqkv_hi[idx] = hi;
    g_Bqkv_lo[idx] = __float2bfloat16(v - __bfloat162float(hi));
}
__global__ void prep_wp_kernel(const float* __restrict__ Wp) {
    int idx = blockIdx.x * 256 + threadIdx.x;      // < 512*512
    float v = Wp[idx];
    __nv_bfloat16 hi = __float2bfloat16(v);
    g_Bp_hi[idx] = hi;
    g_Bp_lo[idx] = __float2bfloat16(v - __bfloat162float(hi));
}
__global__ void split_x_kernel(const float* __restrict__ x) {
    int idx = blockIdx.x * 256 + threadIdx.x;      // < MM*EE
    float v = x[idx];
    __nv_bfloat16 hi = __float2bfloat16(v);
    g_Ax_hi[idx] = hi;
    g_Ax_lo[idx] = __float2bfloat16(v - __bfloat162float(hi));
}

// ---------------------------------------------------------------------------
// mma.sync GEMM: C[128 x 128] tile, 512 threads = 16 warps (4m x 4n),
// per-warp 32x32. 3-pass bf16 hi/lo. 3-stage cp.async pipeline (k=64).
// mode 0: qkv (N=1536) -> bf16 hi/lo Q/K/V. mode 1: proj -> g_proj.
// ---------------------------------------------------------------------------
#define STAGE_BYTES 65536
#define GEMM_SMEM (3 * STAGE_BYTES)   // 196608

__global__ __launch_bounds__(512, 1)
void gemm_mma_kernel(int mode, const float* __restrict__ x,
                     const float* __restrict__ bp) {
    extern __shared__ char sm[];
    const uint32_t smb = smem_u32(sm);
    const int t = threadIdx.x;
    const int w = t >> 5, l = t & 31;
    const int wm = w & 3, wn = w >> 2;          // 4 x 4 warp grid
    const int gid = l >> 2, tig = l & 3;
    const int m0 = blockIdx.x * 128;
    const int n0 = blockIdx.y * 128;

    const __nv_bfloat16* Ah_g = (mode == 0) ? g_Ax_hi : g_Av_hi;
    const __nv_bfloat16* Al_g = (mode == 0) ? g_Ax_lo : g_Av_lo;
    const __nv_bfloat16* Bh_g = (mode == 0) ? g_Bqkv_hi : g_Bp_hi;
    const __nv_bfloat16* Bl_g = (mode == 0) ? g_Bqkv_lo : g_Bp_lo;

    float acc[2][4][4];
#pragma unroll
    for (int i = 0; i < 2; i++)
#pragma unroll
        for (int j = 0; j < 4; j++)
#pragma unroll
            for (int c = 0; c < 4; c++) acc[i][j][c] = 0.f;

    auto issue_stage = [&](int s) {
        const int k0 = s * 64;
        const uint32_t sb = smb + (s % 3) * STAGE_BYTES;
        const __nv_bfloat16* gsrc[4] = {Ah_g, Al_g, Bh_g, Bl_g};
#pragma unroll
        for (int tl = 0; tl < 4; tl++) {
            const uint32_t tbase = sb + tl * 16384;
            const __nv_bfloat16* g = gsrc[tl];
            const int rbase = (tl < 2) ? m0 : n0;
#pragma unroll
            for (int i = 0; i < 2; i++) {
                int c = t + 512 * i;            // 1024 chunks per array
                int row = c >> 3, cb = c & 7;
                uint32_t dst = tbase + sw128((uint32_t)(row * 128 + cb * 16));
                const __nv_bfloat16* src =
                    g + (size_t)(rbase + row) * EE + k0 + cb * 8;
                cpasync16(dst, src);
            }
        }
        commitg();
    };

    issue_stage(0);
    issue_stage(1);

    const int li = l >> 3;
    const int lr = l & 7;

    for (int s = 0; s < 8; s++) {
        if (s < 7) waitg<1>(); else waitg<0>();
        __syncthreads();
        if (s + 2 < 8) issue_stage(s + 2);

        const uint32_t sb = smb + (s % 3) * STAGE_BYTES;

#pragma unroll
        for (int kk = 0; kk < 4; kk++) {
            uint32_t ah[2][4], al[2][4];
#pragma unroll
            for (int mt = 0; mt < 2; mt++) {
                int row = wm * 32 + mt * 16 + (li & 1) * 8 + lr;
                int cb = kk * 2 + (li >> 1);
                uint32_t off = sw128((uint32_t)(row * 128 + cb * 16));
                ldsm4(ah[mt][0], ah[mt][1], ah[mt][2], ah[mt][3], sb + off);
                ldsm4(al[mt][0], al[mt][1], al[mt][2], al[mt][3],
                      sb + 16384 + off);
            }
            uint32_t bh[2][4], bl[2][4];
#pragma unroll
            for (int p2 = 0; p2 < 2; p2++) {
                int nrow = wn * 32 + p2 * 16 + (li >> 1) * 8 + lr;
                int cb = kk * 2 + (li & 1);
                uint32_t off = sw128((uint32_t)(nrow * 128 + cb * 16));
                ldsm4(bh[p2][0], bh[p2][1], bh[p2][2], bh[p2][3],
                      sb + 32768 + off);
                ldsm4(bl[p2][0], bl[p2][1], bl[p2][2], bl[p2][3],
                      sb + 49152 + off);
            }
#pragma unroll
            for (int mt = 0; mt < 2; mt++)
#pragma unroll
                for (int nt = 0; nt < 4; nt++) {
                    int p2 = nt >> 1, od = nt & 1;
                    float* c = acc[mt][nt];
                    mma16816(c, ah[mt], bh[p2][2 * od], bh[p2][2 * od + 1]);
                    mma16816(c, ah[mt], bl[p2][2 * od], bl[p2][2 * od + 1]);
                    mma16816(c, al[mt], bh[p2][2 * od], bh[p2][2 * od + 1]);
                }
        }
    }

    // ---- epilogue ----
    const int row0 = m0 + wm * 32 + gid;
    if (mode == 0) {
#pragma unroll
        for (int mt = 0; mt < 2; mt++) {
            int rg = row0 + mt * 16;
            int b = rg >> 11, sI = rg & 2047;
#pragma unroll
            for (int nt = 0; nt < 4; nt++) {
                int ng = n0 + wn * 32 + nt * 8 + 2 * tig;
                int z = ng >> 9, r9 = ng & 511;
                int h = r9 >> 6, d = r9 & 63;
                __nv_bfloat16* oh = (z == 0) ? g_Qh : ((z == 1) ? g_Kh : g_Vh);
                __nv_bfloat16* ol = (z == 0) ? g_Ql : ((z == 1) ? g_Kl : g_Vl);
                size_t base = (((size_t)(b * HH + h)) * SS + sI) * DD + d;
                uint32_t hi, lo;
                split2(acc[mt][nt][0], acc[mt][nt][1], hi, lo);
                *(uint32_t*)(oh + base) = hi;
                *(uint32_t*)(ol + base) = lo;
                split2(acc[mt][nt][2], acc[mt][nt][3], hi, lo);
                *(uint32_t*)(oh + base + 8 * DD) = hi;
                *(uint32_t*)(ol + base + 8 * DD) = lo;
            }
        }
    } else {
#pragma unroll
        for (int mt = 0; mt < 2; mt++) {
            int rg = row0 + mt * 16;
#pragma unroll
            for (int nt = 0; nt < 4; nt++) {
                int ng = n0 + wn * 32 + nt * 8 + 2 * tig;
                float2 bpv = *(const float2*)(bp + ng);
                float2 x0 = *(const float2*)(x + (size_t)rg * EE + ng);
                float2 x1 = *(const float2*)(x + (size_t)(rg + 8) * EE + ng);
                *(float2*)(g_proj + (size_t)rg * EE + ng) =
                    make_float2(acc[mt][nt][0] + bpv.x + x0.x,
                                acc[mt][nt][1] + bpv.y + x0.y);
                *(float2*)(g_proj + (size_t)(rg + 8) * EE + ng) =
                    make_float2(acc[mt][nt][2] + bpv.x + x1.x,
                                acc[mt][nt][3] + bpv.y + x1.y);
            }
        }
    }
}

// ---------------------------------------------------------------------------
// Flash attention via mma.sync bf16 hi/lo, 512 threads = 16 warps.
// q-tile 256 rows (each warp owns a 16-row strip -> warp-private softmax),
// k-tiles of 64, 3-stage cp.async pipeline. Grid = 128 CTAs (single wave).
// ---------------------------------------------------------------------------
#define NEG_BIG (-1e30f)
#define SM_QH 0
#define SM_QL 32768
#define SM_STG 65536
#define STG_SZ 32768
#define OFF_KH 0
#define OFF_KL 8192
#define OFF_VH 16384
#define OFF_VL 24576
#define ATTN_SMEM (SM_STG + 3 * STG_SZ)   // 163840

__global__ __launch_bounds__(512, 1)
void attn_mma_kernel() {
    extern __shared__ char sm[];
    const uint32_t smb = smem_u32(sm);
    const int t = threadIdx.x;
    const int w = t >> 5, l = t & 31;
    const int gid = l >> 2, tig = l & 3;
    const int li = l >> 3, lr = l & 7;

    const int bid = blockIdx.x;
    const int bh = bid & 15;
    const int qt = 7 - (bid >> 4);        // heavy tiles first
    const int b = bh >> 3, h = bh & 7;
    const int qs = qt * 256;
    const size_t bhoff = (size_t)bh * SS * DD;
    const int ktmax = 4 * qt + 3;

    // ---- issue Q (256x64 hi+lo); joins commit group of stage 0 ----
#pragma unroll
    for (int arr = 0; arr < 2; arr++) {
        const __nv_bfloat16* g = arr ? g_Ql : g_Qh;
        uint32_t base = smb + (arr ? SM_QL : SM_QH);
#pragma unroll
        for (int i = 0; i < 4; i++) {
            int c = t + 512 * i;              // 2048 chunks
            int row = c >> 3, cb = c & 7;
            cpasync16(base + sw128((uint32_t)(row * 128 + cb * 16)),
                      g + bhoff + (size_t)(qs + row) * DD + cb * 8);
        }
    }

    auto issue_stage = [&](int kt) {
        const uint32_t sb = smb + SM_STG + (kt % 3) * STG_SZ;
        const __nv_bfloat16* gs[4] = {g_Kh, g_Kl, g_Vh, g_Vl};
        const int ks = kt * 64;
#pragma unroll
        for (int arr = 0; arr < 4; arr++) {
            int row = t >> 3, cb = t & 7;     // 512 chunks, one per thread
            cpasync16(sb + arr * 8192 + sw128((uint32_t)(row * 128 + cb * 16)),
                      gs[arr] + bhoff + (size_t)(ks + row) * DD + cb * 8);
        }
        commitg();
    };

    issue_stage(0);
    issue_stage(1);

    float O[8][4];
#pragma unroll
    for (int i = 0; i < 8; i++)
#pragma unroll
        for (int j = 0; j < 4; j++) O[i][j] = 0.f;
    float m0 = NEG_BIG, m1 = NEG_BIG, l0 = 0.f, l1 = 0.f;

    const int rowstrip = qs + w * 16;     // this warp's first q row
    const int qg0 = rowstrip + gid;
    const int qg1 = qg0 + 8;

    for (int kt = 0; kt <= ktmax; kt++) {
        if (kt < ktmax) waitg<1>(); else waitg<0>();
        __syncthreads();
        if (kt + 2 <= ktmax) issue_stage(kt + 2);

        const uint32_t sb = smb + SM_STG + (kt % 3) * STG_SZ;
        const int ks = kt * 64;

        // Warp-uniform causal skip: strip fully masked for this k-tile
        if (ks > rowstrip + 15) continue;

        // ---- S = Q K^T (3-pass) ----
        float S[8][4];
#pragma unroll
        for (int i = 0; i < 8; i++)
#pragma unroll
            for (int j = 0; j < 4; j++) S[i][j] = 0.f;

#pragma unroll
        for (int kk = 0; kk < 4; kk++) {
            uint32_t qh[4], ql[4];
            {
                int row = w * 16 + (li & 1) * 8 + lr;
                int cb = kk * 2 + (li >> 1);
                uint32_t off = sw128((uint32_t)(row * 128 + cb * 16));
                ldsm4(qh[0], qh[1], qh[2], qh[3], smb + SM_QH + off);
                ldsm4(ql[0], ql[1], ql[2], ql[3], smb + SM_QL + off);
            }
#pragma unroll
            for (int nb = 0; nb < 4; nb++) {
                uint32_t kh[4], kl[4];
                int nrow = nb * 16 + (li >> 1) * 8 + lr;
                int cb = kk * 2 + (li & 1);
                uint32_t off = sw128((uint32_t)(nrow * 128 + cb * 16));
                ldsm4(kh[0], kh[1], kh[2], kh[3], sb + OFF_KH + off);
                ldsm4(kl[0], kl[1], kl[2], kl[3], sb + OFF_KL + off);
#pragma unroll
                for (int od = 0; od < 2; od++) {
                    float* c = S[nb * 2 + od];
                    mma16816(c, qh, kh[2 * od], kh[2 * od + 1]);
                    mma16816(c, qh, kl[2 * od], kl[2 * od + 1]);
                    mma16816(c, ql, kh[2 * od], kh[2 * od + 1]);
                }
            }
        }

        // ---- causal mask (only when diagonal crosses this strip) ----
        if (ks + 63 > rowstrip) {
#pragma unroll
            for (int nt = 0; nt < 8; nt++) {
                int c0 = ks + nt * 8 + 2 * tig;
                if (c0 > qg0) S[nt][0] = NEG_BIG;
                if (c0 + 1 > qg0) S[nt][1] = NEG_BIG;
                if (c0 > qg1) S[nt][2] = NEG_BIG;
                if (c0 + 1 > qg1) S[nt][3] = NEG_BIG;
            }
        }

        // ---- online softmax (warp-private, rows split by groups of 4 lanes) ----
        float mx0 = NEG_BIG, mx1 = NEG_BIG;
#pragma unroll
        for (int nt = 0; nt < 8; nt++) {
            mx0 = fmaxf(mx0, fmaxf(S[nt][0], S[nt][1]));
            mx1 = fmaxf(mx1, fmaxf(S[nt][2], S[nt][3]));
        }
        mx0 = fmaxf(mx0, __shfl_xor_sync(0xffffffffu, mx0, 1));
        mx0 = fmaxf(mx0, __shfl_xor_sync(0xffffffffu, mx0, 2));
        mx1 = fmaxf(mx1, __shfl_xor_sync(0xffffffffu, mx1, 1));
        mx1 = fmaxf(mx1, __shfl_xor_sync(0xffffffffu, mx1, 2));

        float mn0 = fmaxf(m0, mx0), mn1 = fmaxf(m1, mx1);
        float sc0 = __expf(m0 - mn0), sc1 = __expf(m1 - mn1);
        float rs0 = 0.f, rs1 = 0.f;
#pragma unroll
        for (int nt = 0; nt < 8; nt++) {
            S[nt][0] = __expf(S[nt][0] - mn0);
            S[nt][1] = __expf(S[nt][1] - mn0);
            S[nt][2] = __expf(S[nt][2] - mn1);
            S[nt][3] = __expf(S[nt][3] - mn1);
            rs0 += S[nt][0] + S[nt][1];
            rs1 += S[nt][2] + S[nt][3];
        }
        rs0 += __shfl_xor_sync(0xffffffffu, rs0, 1);
        rs0 += __shfl_xor_sync(0xffffffffu, rs0, 2);
        rs1 += __shfl_xor_sync(0xffffffffu, rs1, 1);
        rs1 += __shfl_xor_sync(0xffffffffu, rs1, 2);
        l0 = l0 * sc0 + rs0;
        l1 = l1 * sc1 + rs1;
        m0 = mn0; m1 = mn1;
#pragma unroll
        for (int dt = 0; dt < 8; dt++) {
            O[dt][0] *= sc0; O[dt][1] *= sc0;
            O[dt][2] *= sc1; O[dt][3] *= sc1;
        }

        // ---- O += P V (3-pass, P from registers) ----
#pragma unroll
        for (int kc = 0; kc < 4; kc++) {
            uint32_t pah[4], pal[4];
            split2(S[2 * kc][0],     S[2 * kc][1],     pah[0], pal[0]);
            split2(S[2 * kc][2],     S[2 * kc][3],     pah[1], pal[1]);
            split2(S[2 * kc + 1][0], S[2 * kc + 1][1], pah[2], pal[2]);
            split2(S[2 * kc + 1][2], S[2 * kc + 1][3], pah[3], pal[3]);
#pragma unroll
            for (int db = 0; db < 4; db++) {
                uint32_t vh[4], vl[4];
                int trow = kc * 16 + (li & 1) * 8 + lr;
                int dcb = (db * 16 + (li >> 1) * 8) * 2;
                uint32_t off = sw128((uint32_t)(trow * 128 + dcb));
                ldsm4t(vh[0], vh[1], vh[2], vh[3], sb + OFF_VH + off);
                ldsm4t(vl[0], vl[1], vl[2], vl[3], sb + OFF_VL + off);
#pragma unroll
                for (int od = 0; od < 2; od++) {
                    float* c = O[db * 2 + od];
                    mma16816(c, pah, vh[2 * od], vh[2 * od + 1]);
                    mma16816(c, pah, vl[2 * od], vl[2 * od + 1]);
                    mma16816(c, pal, vh[2 * od], vh[2 * od + 1]);
                }
            }
        }
    }

    // ---- epilogue: vals[b, s, (7-h)*64+d] as bf16 hi/lo ----
    const float inv0 = 1.f / l0, inv1 = 1.f / l1;
    const int colbase = (HH - 1 - h) * DD;
#pragma unroll
    for (int dt = 0; dt < 8; dt++) {
        int d = dt * 8 + 2 * tig;
        size_t i0 = ((size_t)(b * SS + qg0)) * EE + colbase + d;
        size_t i1 = ((size_t)(b * SS + qg1)) * EE + colbase + d;
        uint32_t hi, lo;
        split2(O[dt][0] * inv0, O[dt][1] * inv0, hi, lo);
        *(uint32_t*)(g_Av_hi + i0) = hi;
        *(uint32_t*)(g_Av_lo + i0) = lo;
        split2(O[dt][2] * inv1, O[dt][3] * inv1, hi, lo);
        *(uint32_t*)(g_Av_hi + i1) = hi;
        *(uint32_t*)(g_Av_lo + i1) = lo;
    }
}

// ---------------------------------------------------------------------------
// LayerNorm per row of 512.
// ---------------------------------------------------------------------------
__global__ void ln_kernel(const float* __restrict__ gamma,
                          const float* __restrict__ beta,
                          float* __restrict__ out) {
    const int row = blockIdx.x;
    const float* v = g_proj + (size_t)row * EE;
    const int t = threadIdx.x;

    float a0 = v[t], a1 = v[t + 256];
    float s = a0 + a1;
    float q = a0 * a0 + a1 * a1;

#pragma unroll
    for (int off = 16; off; off >>= 1) {
        s += __shfl_xor_sync(0xffffffffu, s, off);
        q += __shfl_xor_sync(0xffffffffu, q, off);
    }
    __shared__ float ss[8], sq[8];
    int w = t >> 5, lane = t & 31;
    if (lane == 0) { ss[w] = s; sq[w] = q; }
    __syncthreads();

    float S = 0.f, Q2 = 0.f;
#pragma unroll
    for (int i = 0; i < 8; i++) { S += ss[i]; Q2 += sq[i]; }

    float mu  = S * (1.f / EE);
    float var = Q2 * (1.f / EE) - mu * mu;
    float inv = rsqrtf(var + 1e-5f);

    out[(size_t)row * EE + t]       = (a0 - mu) * inv * gamma[t]       + beta[t];
    out[(size_t)row * EE + t + 256] = (a1 - mu) * inv * gamma[t + 256] + beta[t + 256];
}

// ---------------------------------------------------------------------------
extern "C" void kernel_launch(void* const* d_in, const int* in_sizes, int n_in,
                              void* d_out, int out_size) {
    const float* x     = (const float*)d_in[0];
    const float* Wq    = (const float*)d_in[1];
    const float* Wk    = (const float*)d_in[2];
    const float* Wv    = (const float*)d_in[3];
    const float* Wp    = (const float*)d_in[4];
    const float* bp    = (const float*)d_in[5];
    const float* gamma = (const float*)d_in[6];
    const float* beta  = (const float*)d_in[7];
    float* out = (float*)d_out;

    cudaFuncSetAttribute(gemm_mma_kernel, cudaFuncAttributeMaxDynamicSharedMemorySize, GEMM_SMEM);
    cudaFuncSetAttribute(attn_mma_kernel, cudaFuncAttributeMaxDynamicSharedMemorySize, ATTN_SMEM);

    prep_wqkv_kernel<<<3 * EE * EE / 256, 256>>>(Wq, Wk, Wv);
    prep_wp_kernel<<<EE * EE / 256, 256>>>(Wp);
    split_x_kernel<<<MM * EE / 256, 256>>>(x);

    gemm_mma_kernel<<<dim3(MM / 128, 12), 512, GEMM_SMEM>>>(0, x, bp);
    attn_mma_kernel<<<128, 512, ATTN_SMEM>>>();
    gemm_mma_kernel<<<dim3(MM / 128, 4), 512, GEMM_SMEM>>>(1, x, bp);
    ln_kernel<<<MM, 256>>>(gamma, beta, out);
}

// round 8
// speedup vs baseline: 1.5131x; 1.5131x over previous
#include <cuda_runtime.h>
#include <cuda_fp16.h>
#include <math.h>
#include <stdint.h>

// Problem constants
#define BB 2
#define SS 2048
#define EE 512
#define HH 8
#define DD 64
#define MM (BB * SS)   // 4096 rows

// Scratch (device globals; no allocation allowed)
__device__ float g_proj[MM * EE];

// fp16 operand arrays
__device__ __align__(16) __half g_Ax_hi[MM * EE];       // x split (qkv gemm A)
__device__ __align__(16) __half g_Ax_lo[MM * EE];
__device__ __align__(16) __half g_Qh[16 * 2048 * 64];   // [bh][s][d]
__device__ __align__(16) __half g_Ql[16 * 2048 * 64];
__device__ __align__(16) __half g_Kh[16 * 2048 * 64];
__device__ __align__(16) __half g_Kl[16 * 2048 * 64];
__device__ __align__(16) __half g_Vh[16 * 2048 * 64];   // single fp16
__device__ __align__(16) __half g_Av[MM * EE];          // attention out, single fp16
__device__ __align__(16) __half g_Bqkv_hi[3 * EE * EE]; // [n=z*512+h*64+d][e]
__device__ __align__(16) __half g_Bqkv_lo[3 * EE * EE];
__device__ __align__(16) __half g_Bp_hi[EE * EE];       // [n][k] = Wp[n][k]
__device__ __align__(16) __half g_Bp_lo[EE * EE];

// ---------------------------------------------------------------------------
// helpers
// ---------------------------------------------------------------------------
__device__ __forceinline__ uint32_t smem_u32(const void* p) {
    uint32_t a;
    asm("{ .reg .u64 t; cvta.to.shared.u64 t, %1; cvt.u32.u64 %0, t; }"
        : "=r"(a) : "l"(p));
    return a;
}
__device__ __forceinline__ uint32_t sw128(uint32_t off) {
    return off ^ ((off >> 3) & 0x70);
}
__device__ __forceinline__ void cpasync16(uint32_t dst, const void* src) {
    asm volatile("cp.async.cg.shared.global [%0], [%1], 16;"
                 :: "r"(dst), "l"(src) : "memory");
}
template <int N>
__device__ __forceinline__ void waitg() {
    asm volatile("cp.async.wait_group %0;" :: "n"(N) : "memory");
}
__device__ __forceinline__ void commitg() {
    asm volatile("cp.async.commit_group;" ::: "memory");
}
__device__ __forceinline__ void ldsm4(uint32_t& r0, uint32_t& r1, uint32_t& r2,
                                      uint32_t& r3, uint32_t a) {
    asm volatile("ldmatrix.sync.aligned.m8n8.x4.shared.b16 {%0,%1,%2,%3}, [%4];"
                 : "=r"(r0), "=r"(r1), "=r"(r2), "=r"(r3) : "r"(a));
}
__device__ __forceinline__ void ldsm4t(uint32_t& r0, uint32_t& r1, uint32_t& r2,
                                       uint32_t& r3, uint32_t a) {
    asm volatile("ldmatrix.sync.aligned.m8n8.x4.trans.shared.b16 {%0,%1,%2,%3}, [%4];"
                 : "=r"(r0), "=r"(r1), "=r"(r2), "=r"(r3) : "r"(a));
}
__device__ __forceinline__ void mma16816(float* c, const uint32_t* a,
                                         uint32_t b0, uint32_t b1) {
    asm volatile(
        "mma.sync.aligned.m16n8k16.row.col.f32.f16.f16.f32 "
        "{%0,%1,%2,%3}, {%4,%5,%6,%7}, {%8,%9}, {%0,%1,%2,%3};"
        : "+f"(c[0]), "+f"(c[1]), "+f"(c[2]), "+f"(c[3])
        : "r"(a[0]), "r"(a[1]), "r"(a[2]), "r"(a[3]), "r"(b0), "r"(b1));
}
__device__ __forceinline__ uint32_t packh2(float a, float b) {
    __half ha = __float2half_rn(a), hb = __float2half_rn(b);
    return (uint32_t)__half_as_ushort(ha) |
           ((uint32_t)__half_as_ushort(hb) << 16);
}
__device__ __forceinline__ void split2h(float a, float b, uint32_t& hi, uint32_t& lo) {
    __half ha = __float2half_rn(a), hb = __float2half_rn(b);
    float ra = a - __half2float(ha), rb = b - __half2float(hb);
    hi = (uint32_t)__half_as_ushort(ha) |
         ((uint32_t)__half_as_ushort(hb) << 16);
    __half la = __float2half_rn(ra), lb = __float2half_rn(rb);
    lo = (uint32_t)__half_as_ushort(la) |
         ((uint32_t)__half_as_ushort(lb) << 16);
}

// ---------------------------------------------------------------------------
// Prep: weights + x -> fp16 hi/lo
// ---------------------------------------------------------------------------
__global__ void prep_wqkv_kernel(const float* __restrict__ Wq,
                                 const float* __restrict__ Wk,
                                 const float* __restrict__ Wv) {
    int idx = blockIdx.x * 256 + threadIdx.x;      // < 3*512*512
    int n = idx >> 9, e = idx & 511;
    int z = n >> 9, h = (n >> 6) & 7, d = n & 63;
    const float* W = (z == 0) ? Wq : ((z == 1) ? Wk : Wv);
    float v = W[((size_t)h * EE + e) * DD + d];
    __half hi = __float2half_rn(v);
    g_Bqkv_hi[idx] = hi;
    g_Bqkv_lo[idx] = __float2half_rn(v - __half2float(hi));
}
__global__ void prep_wp_kernel(const float* __restrict__ Wp) {
    int idx = blockIdx.x * 256 + threadIdx.x;      // < 512*512
    float v = Wp[idx];
    __half hi = __float2half_rn(v);
    g_Bp_hi[idx] = hi;
    g_Bp_lo[idx] = __float2half_rn(v - __half2float(hi));
}
__global__ void split_x_kernel(const float* __restrict__ x) {
    int idx = blockIdx.x * 256 + threadIdx.x;      // < MM*EE
    float v = x[idx];
    __half hi = __float2half_rn(v);
    g_Ax_hi[idx] = hi;
    g_Ax_lo[idx] = __float2half_rn(v - __half2float(hi));
}

// ---------------------------------------------------------------------------
// mma.sync GEMM: C[128 x 128] tile of A[M x 512] * B[N x 512]^T
// mode 0: qkv (N=1536), A hi/lo 3-pass -> Q/K hi/lo fp16, V single fp16.
// mode 1: proj (N=512), A = g_Av single fp16, 2-pass -> g_proj = acc+bp+x.
// 256 threads = 8 warps (4m x 2n). 3-stage cp.async pipeline (k=64).
// ---------------------------------------------------------------------------
#define STAGE_BYTES 65536
#define GEMM_SMEM (3 * STAGE_BYTES)   // 196608

__global__ __launch_bounds__(256, 1)
void gemm_mma_kernel(int mode, const float* __restrict__ x,
                     const float* __restrict__ bp) {
    extern __shared__ char sm[];
    const uint32_t smb = smem_u32(sm);
    const int t = threadIdx.x;
    const int w = t >> 5, l = t & 31;
    const int wm = w & 3, wn = w >> 2;
    const int gid = l >> 2, tig = l & 3;
    const int m0 = blockIdx.x * 128;
    const int n0 = blockIdx.y * 128;

    const __half* Ah_g = (mode == 0) ? g_Ax_hi : g_Av;
    const __half* Al_g = g_Ax_lo;                      // unused in mode 1
    const __half* Bh_g = (mode == 0) ? g_Bqkv_hi : g_Bp_hi;
    const __half* Bl_g = (mode == 0) ? g_Bqkv_lo : g_Bp_lo;

    float acc[2][8][4];
#pragma unroll
    for (int i = 0; i < 2; i++)
#pragma unroll
        for (int j = 0; j < 8; j++)
#pragma unroll
            for (int c = 0; c < 4; c++) acc[i][j][c] = 0.f;

    auto issue_stage = [&](int s) {
        const int k0 = s * 64;
        const uint32_t sb = smb + (s % 3) * STAGE_BYTES;
        const __half* gsrc[4] = {Ah_g, Al_g, Bh_g, Bl_g};
#pragma unroll
        for (int tl = 0; tl < 4; tl++) {
            if (mode == 1 && tl == 1) continue;        // no A_lo in proj
            const uint32_t tbase = sb + tl * 16384;
            const __half* g = gsrc[tl];
            const int rbase = (tl < 2) ? m0 : n0;
#pragma unroll
            for (int i = 0; i < 4; i++) {
                int c = t + 256 * i;
                int row = c >> 3, cb = c & 7;
                uint32_t dst = tbase + sw128((uint32_t)(row * 128 + cb * 16));
                const __half* src =
                    g + (size_t)(rbase + row) * EE + k0 + cb * 8;
                cpasync16(dst, src);
            }
        }
        commitg();
    };

    issue_stage(0);
    issue_stage(1);

    const int li = l >> 3;
    const int lr = l & 7;

    for (int s = 0; s < 8; s++) {
        if (s < 7) waitg<1>(); else waitg<0>();
        __syncthreads();
        if (s + 2 < 8) issue_stage(s + 2);

        const uint32_t sb = smb + (s % 3) * STAGE_BYTES;

#pragma unroll
        for (int kk = 0; kk < 4; kk++) {
            uint32_t ah[2][4], al[2][4];
#pragma unroll
            for (int mt = 0; mt < 2; mt++) {
                int row = wm * 32 + mt * 16 + (li & 1) * 8 + lr;
                int cb = kk * 2 + (li >> 1);
                uint32_t off = sw128((uint32_t)(row * 128 + cb * 16));
                ldsm4(ah[mt][0], ah[mt][1], ah[mt][2], ah[mt][3], sb + off);
                if (mode == 0)
                    ldsm4(al[mt][0], al[mt][1], al[mt][2], al[mt][3],
                          sb + 16384 + off);
            }
#pragma unroll
            for (int h2 = 0; h2 < 2; h2++) {
                uint32_t bh[2][4], bl[2][4];
#pragma unroll
                for (int p2 = 0; p2 < 2; p2++) {
                    int ntb = h2 * 2 + p2;
                    int nrow = wn * 64 + ntb * 16 + (li >> 1) * 8 + lr;
                    int cb = kk * 2 + (li & 1);
                    uint32_t off = sw128((uint32_t)(nrow * 128 + cb * 16));
                    ldsm4(bh[p2][0], bh[p2][1], bh[p2][2], bh[p2][3],
                          sb + 32768 + off);
                    ldsm4(bl[p2][0], bl[p2][1], bl[p2][2], bl[p2][3],
                          sb + 49152 + off);
                }
#pragma unroll
                for (int mt = 0; mt < 2; mt++)
#pragma unroll
                    for (int q = 0; q < 4; q++) {
                        int nt = h2 * 4 + q;
                        int p2 = q >> 1, od = q & 1;
                        float* c = acc[mt][nt];
                        mma16816(c, ah[mt], bh[p2][2 * od], bh[p2][2 * od + 1]);
                        mma16816(c, ah[mt], bl[p2][2 * od], bl[p2][2 * od + 1]);
                        if (mode == 0)
                            mma16816(c, al[mt], bh[p2][2 * od], bh[p2][2 * od + 1]);
                    }
            }
        }
    }

    // ---- epilogue ----
    const int row0 = m0 + wm * 32 + gid;
    if (mode == 0) {
#pragma unroll
        for (int mt = 0; mt < 2; mt++) {
            int rg = row0 + mt * 16;
            int b = rg >> 11, sI = rg & 2047;
#pragma unroll
            for (int nt = 0; nt < 8; nt++) {
                int ng = n0 + wn * 64 + nt * 8 + 2 * tig;
                int z = ng >> 9, r9 = ng & 511;
                int h = r9 >> 6, d = r9 & 63;
                size_t base = (((size_t)(b * HH + h)) * SS + sI) * DD + d;
                if (z == 2) {
                    *(uint32_t*)(g_Vh + base) =
                        packh2(acc[mt][nt][0], acc[mt][nt][1]);
                    *(uint32_t*)(g_Vh + base + 8 * DD) =
                        packh2(acc[mt][nt][2], acc[mt][nt][3]);
                } else {
                    __half* oh = (z == 0) ? g_Qh : g_Kh;
                    __half* ol = (z == 0) ? g_Ql : g_Kl;
                    uint32_t hi, lo;
                    split2h(acc[mt][nt][0], acc[mt][nt][1], hi, lo);
                    *(uint32_t*)(oh + base) = hi;
                    *(uint32_t*)(ol + base) = lo;
                    split2h(acc[mt][nt][2], acc[mt][nt][3], hi, lo);
                    *(uint32_t*)(oh + base + 8 * DD) = hi;
                    *(uint32_t*)(ol + base + 8 * DD) = lo;
                }
            }
        }
    } else {
#pragma unroll
        for (int mt = 0; mt < 2; mt++) {
            int rg = row0 + mt * 16;
#pragma unroll
            for (int nt = 0; nt < 8; nt++) {
                int ng = n0 + wn * 64 + nt * 8 + 2 * tig;
                float2 bpv = *(const float2*)(bp + ng);
                float2 x0 = *(const float2*)(x + (size_t)rg * EE + ng);
                float2 x1 = *(const float2*)(x + (size_t)(rg + 8) * EE + ng);
                *(float2*)(g_proj + (size_t)rg * EE + ng) =
                    make_float2(acc[mt][nt][0] + bpv.x + x0.x,
                                acc[mt][nt][1] + bpv.y + x0.y);
                *(float2*)(g_proj + (size_t)(rg + 8) * EE + ng) =
                    make_float2(acc[mt][nt][2] + bpv.x + x1.x,
                                acc[mt][nt][3] + bpv.y + x1.y);
            }
        }
    }
}

// ---------------------------------------------------------------------------
// Flash attention: fp16 mma. QK^T 3-pass (Q,K hi/lo); PV 2-pass (P hi/lo,
// V single fp16). q-tile 128 rows, k-tiles of 64, 8 warps, 3-stage pipeline.
// ---------------------------------------------------------------------------
#define NEG_BIG (-1e30f)
#define SM_QH 0
#define SM_QL 16384
#define SM_STG 32768
#define STG_SZ 24576          // Kh 8K + Kl 8K + V 8K
#define OFF_KH 0
#define OFF_KL 8192
#define OFF_V 16384
#define ATTN_SMEM (SM_STG + 3 * STG_SZ)   // 106496

__global__ __launch_bounds__(256, 1)
void attn_mma_kernel() {
    extern __shared__ char sm[];
    const uint32_t smb = smem_u32(sm);
    const int t = threadIdx.x;
    const int w = t >> 5, l = t & 31;
    const int gid = l >> 2, tig = l & 3;
    const int li = l >> 3, lr = l & 7;

    const int bid = blockIdx.x;
    const int bh = bid & 15;
    const int qt = 15 - (bid >> 4);       // heavy tiles first
    const int b = bh >> 3, h = bh & 7;
    const int qs = qt * 128;
    const size_t bhoff = (size_t)bh * SS * DD;
    const int ktmax = 2 * qt + 1;

    // ---- issue Q (128x64 hi+lo); joins commit group of stage 0 ----
#pragma unroll
    for (int arr = 0; arr < 2; arr++) {
        const __half* g = arr ? g_Ql : g_Qh;
        uint32_t base = smb + (arr ? SM_QL : SM_QH);
#pragma unroll
        for (int i = 0; i < 4; i++) {
            int c = t + 256 * i;
            int row = c >> 3, cb = c & 7;
            cpasync16(base + sw128((uint32_t)(row * 128 + cb * 16)),
                      g + bhoff + (size_t)(qs + row) * DD + cb * 8);
        }
    }

    auto issue_stage = [&](int kt) {
        const uint32_t sb = smb + SM_STG + (kt % 3) * STG_SZ;
        const __half* gs[3] = {g_Kh, g_Kl, g_Vh};
        const int ks = kt * 64;
#pragma unroll
        for (int arr = 0; arr < 3; arr++) {
#pragma unroll
            for (int i = 0; i < 2; i++) {
                int c = t + 256 * i;          // 512 chunks per array
                int row = c >> 3, cb = c & 7;
                cpasync16(sb + arr * 8192 + sw128((uint32_t)(row * 128 + cb * 16)),
                          gs[arr] + bhoff + (size_t)(ks + row) * DD + cb * 8);
            }
        }
        commitg();
    };

    issue_stage(0);
    issue_stage(1);

    float O[8][4];
#pragma unroll
    for (int i = 0; i < 8; i++)
#pragma unroll
        for (int j = 0; j < 4; j++) O[i][j] = 0.f;
    float m0 = NEG_BIG, m1 = NEG_BIG, l0 = 0.f, l1 = 0.f;

    const int qg0 = qs + w * 16 + gid;
    const int qg1 = qg0 + 8;

    for (int kt = 0; kt <= ktmax; kt++) {
        if (kt < ktmax) waitg<1>(); else waitg<0>();
        __syncthreads();
        if (kt + 2 <= ktmax) issue_stage(kt + 2);

        const uint32_t sb = smb + SM_STG + (kt % 3) * STG_SZ;
        const int ks = kt * 64;

        // ---- S = Q K^T (3-pass fp16 hi/lo) ----
        float S[8][4];
#pragma unroll
        for (int i = 0; i < 8; i++)
#pragma unroll
            for (int j = 0; j < 4; j++) S[i][j] = 0.f;

#pragma unroll
        for (int kk = 0; kk < 4; kk++) {
            uint32_t qh[4], ql[4];
            {
                int row = w * 16 + (li & 1) * 8 + lr;
                int cb = kk * 2 + (li >> 1);
                uint32_t off = sw128((uint32_t)(row * 128 + cb * 16));
                ldsm4(qh[0], qh[1], qh[2], qh[3], smb + SM_QH + off);
                ldsm4(ql[0], ql[1], ql[2], ql[3], smb + SM_QL + off);
            }
#pragma unroll
            for (int nb = 0; nb < 4; nb++) {
                uint32_t kh[4], kl[4];
                int nrow = nb * 16 + (li >> 1) * 8 + lr;
                int cb = kk * 2 + (li & 1);
                uint32_t off = sw128((uint32_t)(nrow * 128 + cb * 16));
                ldsm4(kh[0], kh[1], kh[2], kh[3], sb + OFF_KH + off);
                ldsm4(kl[0], kl[1], kl[2], kl[3], sb + OFF_KL + off);
#pragma unroll
                for (int od = 0; od < 2; od++) {
                    float* c = S[nb * 2 + od];
                    mma16816(c, qh, kh[2 * od], kh[2 * od + 1]);
                    mma16816(c, qh, kl[2 * od], kl[2 * od + 1]);
                    mma16816(c, ql, kh[2 * od], kh[2 * od + 1]);
                }
            }
        }

        // ---- causal mask ----
        if (ks + 63 > qs + w * 16) {
#pragma unroll
            for (int nt = 0; nt < 8; nt++) {
                int c0 = ks + nt * 8 + 2 * tig;
                if (c0 > qg0) S[nt][0] = NEG_BIG;
                if (c0 + 1 > qg0) S[nt][1] = NEG_BIG;
                if (c0 > qg1) S[nt][2] = NEG_BIG;
                if (c0 + 1 > qg1) S[nt][3] = NEG_BIG;
            }
        }

        // ---- online softmax ----
        float mx0 = NEG_BIG, mx1 = NEG_BIG;
#pragma unroll
        for (int nt = 0; nt < 8; nt++) {
            mx0 = fmaxf(mx0, fmaxf(S[nt][0], S[nt][1]));
            mx1 = fmaxf(mx1, fmaxf(S[nt][2], S[nt][3]));
        }
        mx0 = fmaxf(mx0, __shfl_xor_sync(0xffffffffu, mx0, 1));
        mx0 = fmaxf(mx0, __shfl_xor_sync(0xffffffffu, mx0, 2));
        mx1 = fmaxf(mx1, __shfl_xor_sync(0xffffffffu, mx1, 1));
        mx1 = fmaxf(mx1, __shfl_xor_sync(0xffffffffu, mx1, 2));

        float mn0 = fmaxf(m0, mx0), mn1 = fmaxf(m1, mx1);
        float sc0 = __expf(m0 - mn0), sc1 = __expf(m1 - mn1);
        float rs0 = 0.f, rs1 = 0.f;
#pragma unroll
        for (int nt = 0; nt < 8; nt++) {
            S[nt][0] = __expf(S[nt][0] - mn0);
            S[nt][1] = __expf(S[nt][1] - mn0);
            S[nt][2] = __expf(S[nt][2] - mn1);
            S[nt][3] = __expf(S[nt][3] - mn1);
            rs0 += S[nt][0] + S[nt][1];
            rs1 += S[nt][2] + S[nt][3];
        }
        rs0 += __shfl_xor_sync(0xffffffffu, rs0, 1);
        rs0 += __shfl_xor_sync(0xffffffffu, rs0, 2);
        rs1 += __shfl_xor_sync(0xffffffffu, rs1, 1);
        rs1 += __shfl_xor_sync(0xffffffffu, rs1, 2);
        l0 = l0 * sc0 + rs0;
        l1 = l1 * sc1 + rs1;
        m0 = mn0; m1 = mn1;
#pragma unroll
        for (int dt = 0; dt < 8; dt++) {
            O[dt][0] *= sc0; O[dt][1] *= sc0;
            O[dt][2] *= sc1; O[dt][3] *= sc1;
        }

        // ---- O += P V (2-pass: P hi/lo x single-fp16 V) ----
#pragma unroll
        for (int kc = 0; kc < 4; kc++) {
            uint32_t pah[4], pal[4];
            split2h(S[2 * kc][0],     S[2 * kc][1],     pah[0], pal[0]);
            split2h(S[2 * kc][2],     S[2 * kc][3],     pah[1], pal[1]);
            split2h(S[2 * kc + 1][0], S[2 * kc + 1][1], pah[2], pal[2]);
            split2h(S[2 * kc + 1][2], S[2 * kc + 1][3], pah[3], pal[3]);
#pragma unroll
            for (int db = 0; db < 4; db++) {
                uint32_t vh[4];
                int trow = kc * 16 + (li & 1) * 8 + lr;
                int dcb = (db * 16 + (li >> 1) * 8) * 2;
                uint32_t off = sw128((uint32_t)(trow * 128 + dcb));
                ldsm4t(vh[0], vh[1], vh[2], vh[3], sb + OFF_V + off);
#pragma unroll
                for (int od = 0; od < 2; od++) {
                    float* c = O[db * 2 + od];
                    mma16816(c, pah, vh[2 * od], vh[2 * od + 1]);
                    mma16816(c, pal, vh[2 * od], vh[2 * od + 1]);
                }
            }
        }
    }

    // ---- epilogue: vals[b, s, (7-h)*64+d] as single fp16 ----
    const float inv0 = 1.f / l0, inv1 = 1.f / l1;
    const int colbase = (HH - 1 - h) * DD;
#pragma unroll
    for (int dt = 0; dt < 8; dt++) {
        int d = dt * 8 + 2 * tig;
        size_t i0 = ((size_t)(b * SS + qg0)) * EE + colbase + d;
        size_t i1 = ((size_t)(b * SS + qg1)) * EE + colbase + d;
        *(uint32_t*)(g_Av + i0) = packh2(O[dt][0] * inv0, O[dt][1] * inv0);
        *(uint32_t*)(g_Av + i1) = packh2(O[dt][2] * inv1, O[dt][3] * inv1);
    }
}

// ---------------------------------------------------------------------------
// LayerNorm per row of 512.
// ---------------------------------------------------------------------------
__global__ void ln_kernel(const float* __restrict__ gamma,
                          const float* __restrict__ beta,
                          float* __restrict__ out) {
    const int row = blockIdx.x;
    const float* v = g_proj + (size_t)row * EE;
    const int t = threadIdx.x;

    float a0 = v[t], a1 = v[t + 256];
    float s = a0 + a1;
    float q = a0 * a0 + a1 * a1;

#pragma unroll
    for (int off = 16; off; off >>= 1) {
        s += __shfl_xor_sync(0xffffffffu, s, off);
        q += __shfl_xor_sync(0xffffffffu, q, off);
    }
    __shared__ float ss[8], sq[8];
    int w = t >> 5, lane = t & 31;
    if (lane == 0) { ss[w] = s; sq[w] = q; }
    __syncthreads();

    float S = 0.f, Q2 = 0.f;
#pragma unroll
    for (int i = 0; i < 8; i++) { S += ss[i]; Q2 += sq[i]; }

    float mu  = S * (1.f / EE);
    float var = Q2 * (1.f / EE) - mu * mu;
    float inv = rsqrtf(var + 1e-5f);

    out[(size_t)row * EE + t]       = (a0 - mu) * inv * gamma[t]       + beta[t];
    out[(size_t)row * EE + t + 256] = (a1 - mu) * inv * gamma[t + 256] + beta[t + 256];
}

// ---------------------------------------------------------------------------
extern "C" void kernel_launch(void* const* d_in, const int* in_sizes, int n_in,
                              void* d_out, int out_size) {
    const float* x     = (const float*)d_in[0];
    const float* Wq    = (const float*)d_in[1];
    const float* Wk    = (const float*)d_in[2];
    const float* Wv    = (const float*)d_in[3];
    const float* Wp    = (const float*)d_in[4];
    const float* bp    = (const float*)d_in[5];
    const float* gamma = (const float*)d_in[6];
    const float* beta  = (const float*)d_in[7];
    float* out = (float*)d_out;

    cudaFuncSetAttribute(gemm_mma_kernel, cudaFuncAttributeMaxDynamicSharedMemorySize, GEMM_SMEM);
    cudaFuncSetAttribute(attn_mma_kernel, cudaFuncAttributeMaxDynamicSharedMemorySize, ATTN_SMEM);

    prep_wqkv_kernel<<<3 * EE * EE / 256, 256>>>(Wq, Wk, Wv);
    prep_wp_kernel<<<EE * EE / 256, 256>>>(Wp);
    split_x_kernel<<<MM * EE / 256, 256>>>(x);

    gemm_mma_kernel<<<dim3(MM / 128, 12), 256, GEMM_SMEM>>>(0, x, bp);
    attn_mma_kernel<<<256, 256, ATTN_SMEM>>>();
    gemm_mma_kernel<<<dim3(MM / 128, 4), 256, GEMM_SMEM>>>(1, x, bp);
    ln_kernel<<<MM, 256>>>(gamma, beta, out);
}